// round 11
// baseline (speedup 1.0000x reference)
#include <cuda_runtime.h>
#include <cuda_fp16.h>
#include <cstdint>
#include <math.h>

#define NB 32
#define NN 512
#define NH 256
#define NPLANES 96
#define HALF ((size_t)NN * NH)   // 512*256

// ---------------- device globals (no allocation allowed) ----------------
// DCT matrices (x16 vs orthonormal: element = cos), single-rounded fp16
__device__ __align__(1024) __half g_De[NH * NH];   // even-k rows [r][h]
__device__ __align__(1024) __half g_Do[NH * NH];   // odd-k rows
// folded input, single-rounded fp16: [p=3b+c][w][h']
__device__ __align__(1024) __half g_xe[NPLANES * HALF], g_xo[NPLANES * HALF];
// folded intermediate (x16 scale), fp16: [p][k'][w']  (k' = parity*256 + half-index)
__device__ __align__(1024) __half g_te[NPLANES * HALF], g_to[NPLANES * HALF];

// ---------------- helpers ----------------
__device__ __forceinline__ uint32_t smem_to_u32(const void* smem_ptr) {
    uint32_t addr;
    asm("{ .reg .u64 tmp; cvta.to.shared.u64 tmp, %1; cvt.u32.u64 %0, tmp; }"
        : "=r"(addr) : "l"(smem_ptr));
    return addr;
}
#define CP_ASYNC_16(saddr, gptr) \
    asm volatile("cp.async.cg.shared.global [%0], [%1], 16;" \
        :: "r"((uint32_t)(saddr)), "l"(gptr) : "memory")
#define CP_COMMIT() asm volatile("cp.async.commit_group;" ::: "memory")
#define CP_WAIT(n)  asm volatile("cp.async.wait_group %0;" :: "n"(n) : "memory")

__device__ __forceinline__ void ldsm4(uint32_t r[4], uint32_t addr) {
    asm volatile("ldmatrix.sync.aligned.m8n8.x4.shared.b16 {%0,%1,%2,%3}, [%4];"
        : "=r"(r[0]), "=r"(r[1]), "=r"(r[2]), "=r"(r[3]) : "r"(addr));
}
__device__ __forceinline__ void mma16816(float c[4], const uint32_t a[4],
                                         uint32_t b0, uint32_t b1) {
    asm volatile(
        "mma.sync.aligned.m16n8k16.row.col.f32.f16.f16.f32 "
        "{%0,%1,%2,%3}, {%4,%5,%6,%7}, {%8,%9}, {%0,%1,%2,%3};"
        : "+f"(c[0]), "+f"(c[1]), "+f"(c[2]), "+f"(c[3])
        : "r"(a[0]), "r"(a[1]), "r"(a[2]), "r"(a[3]), "r"(b0), "r"(b1));
}

// -------- kernel 0: half-size DCT matrices (x16 scale), fp16 --------
__global__ void init_dct_half() {
    int idx = blockIdx.x * blockDim.x + threadIdx.x;   // 256*256 threads
    int r = idx >> 8;
    int h = idx & 255;
    int me = ((2 * h + 1) * (2 * r)) & 2047;
    float ve = cospif((float)me * (1.0f / 1024.0f));
    if (r == 0) ve *= 0.70710678118654752440f;
    g_De[idx] = __float2half(ve);
    int mo = ((2 * h + 1) * (2 * r + 1)) & 2047;
    g_Do[idx] = __float2half(cospif((float)mo * (1.0f / 1024.0f)));
}

// -------- kernel 1: de-interleave + transpose + h-fold + single fp16 round --------
// x[b][h][w][c] fp32 -> xe/xo fp16 [p=3b+c][w][h'<256]
__global__ __launch_bounds__(256) void fold_split_x(const float* __restrict__ x) {
    __shared__ float tA[3][32][33];
    __shared__ float tB[3][32][33];
    const int tid = threadIdx.x;
    const int b = blockIdx.z, h0 = blockIdx.y * 32, w0 = blockIdx.x * 32;
    const float* baseA = x + (((size_t)b * NN + h0) * NN + w0) * 3;
    const float* baseB = x + (((size_t)b * NN + (480 - h0)) * NN + w0) * 3;

    for (int i = tid; i < 768; i += 256) {             // 32 rows x 24 float4
        int row = i / 24, f4 = i % 24;
        float4 va = *(const float4*)(baseA + (size_t)row * NN * 3 + f4 * 4);
        float4 vb = *(const float4*)(baseB + (size_t)row * NN * 3 + f4 * 4);
        int f = f4 * 4;
        tA[(f + 0) % 3][(f + 0) / 3][row] = va.x;
        tA[(f + 1) % 3][(f + 1) / 3][row] = va.y;
        tA[(f + 2) % 3][(f + 2) / 3][row] = va.z;
        tA[(f + 3) % 3][(f + 3) / 3][row] = va.w;
        tB[(f + 0) % 3][(f + 0) / 3][row] = vb.x;
        tB[(f + 1) % 3][(f + 1) / 3][row] = vb.y;
        tB[(f + 2) % 3][(f + 2) / 3][row] = vb.z;
        tB[(f + 3) % 3][(f + 3) / 3][row] = vb.w;
    }
    __syncthreads();

    const int wl = tid >> 3;
    const int hs = (tid & 7) * 4;
#pragma unroll
    for (int c = 0; c < 3; c++) {
        size_t p = (size_t)(b * 3 + c);
        size_t dst = (p * NN + (w0 + wl)) * NH + h0 + hs;
        union { __half v[4]; uint2 u; } ue, uo;
#pragma unroll
        for (int j = 0; j < 4; j++) {
            int hr = hs + j;
            float a = tA[c][wl][hr];
            float m = tB[c][wl][31 - hr];     // x[511-(h0+hr)]
            ue.v[j] = __float2half(a + m);
            uo.v[j] = __float2half(a - m);
        }
        *(uint2*)&g_xe[dst] = ue.u;
        *(uint2*)&g_xo[dst] = uo.u;
    }
}

// ---------------- HMMA GEMM, K=256, single fp16 product ----------------
// PASS 1: t[k'][w] = (De|Do) @ (xe|xo); CTA covers w'-tile AND its mirror,
//         epilogue folds w <-> 511-w and writes te/to fp16 directly.
// PASS 2: out = (te|to) @ (De|Do)^T, parity-interleaved columns, x(1/256).
// stage slots (8KB each, 128 rows x 64B, SW64):
//   PASS1: 0=M  1=X(two 64-row blocks)   PASS2: 0=te 1=to 2=B(De|Do)
#define MAT_BYTES   8192
#define STAGE_BYTES(P) ((P) == 1 ? 16384 : 24576)
#define NCHUNK      8
#define GEMM_SMEM_TOTAL 69632   // epilogue 128*132*4 = 67584 dominates

template <int PASS>
__global__ __launch_bounds__(256, 2)
void gemm_hmma_kernel(float* __restrict__ Out) {
    extern __shared__ char smem[];
    const uint32_t smem_base = smem_to_u32(smem);
    const int tid  = threadIdx.x;
    const int wid  = tid >> 5;
    const int lane = tid & 31;
    const int p  = blockIdx.z;

    const __half *pA0, *pA1 = nullptr, *pB0, *pB0b;
    int m0, n0, parity = 0;
    if (PASS == 1) {
        parity = blockIdx.y >> 1;
        m0 = (blockIdx.y & 1) * 128;
        n0 = blockIdx.x * 64;                  // w' tile base (64 wide + mirror)
        pA0 = (parity ? g_Do : g_De) + (size_t)m0 * NH;
        const __half* xpar = (parity ? g_xo : g_xe) + (size_t)p * HALF;
        pB0  = xpar + (size_t)n0 * NH;                    // rows 0..63: w' = n0+r
        pB0b = xpar + ((size_t)(384 - n0)) * NH;          // rows 64..127: w = 448-n0+(r-64)
    } else {
        m0 = blockIdx.y * 128;                 // k' tile
        n0 = blockIdx.x * 64;                  // l'' offset (final l tile = 2*n0)
        pA0 = g_te + (size_t)p * HALF + (size_t)m0 * NH;
        pA1 = g_to + (size_t)p * HALF + (size_t)m0 * NH;
        pB0  = g_De + (size_t)n0 * NH;                    // rows 0..63
        pB0b = g_Do + ((long long)n0 - 64) * NH;          // rows 64..127
    }

    const int wm = wid & 3;
    const int wn = wid >> 2;

    float acc[2][8][4];
#pragma unroll
    for (int t = 0; t < 2; t++)
#pragma unroll
        for (int nt = 0; nt < 8; nt++)
#pragma unroll
            for (int r = 0; r < 4; r++) acc[t][nt][r] = 0.0f;

    constexpr int NSLOT = (PASS == 1) ? 2 : 3;
    constexpr int NCOPY = NSLOT * 512;
    constexpr int BSLOT = NSLOT - 1;
    auto copy_chunk = [&](int ch, int s) {
        const int k0c = ch * 32;
        const uint32_t sb = smem_base + s * STAGE_BYTES(PASS);
        for (int i = tid; i < NCOPY; i += 256) {
            int slot = i >> 9;
            int seg  = i & 511;
            int r    = seg >> 2;
            int c16  = seg & 3;
            const __half* src;
            if (slot == 0)          src = pA0;
            else if (slot < BSLOT)  src = pA1;
            else                    src = (r < 64) ? pB0 : pB0b;
            uint32_t off = (uint32_t)(r * 64 + c16 * 16);
            uint32_t sw  = off ^ ((off >> 3) & 0x30);   // SW64
            CP_ASYNC_16(sb + slot * MAT_BYTES + sw, src + (size_t)r * NH + k0c + c16 * 8);
        }
    };

    // ldmatrix lane geometry (SW64, 64B rows)
    const int arow = wm * 32 + (lane & 15);
    const int acol = lane >> 4;
    const int brow = wn * 64 + (lane & 7) + ((lane >> 4) << 3);
    const int bcol = (lane >> 3) & 1;
    const uint32_t abase = (PASS == 2 && wn) ? (uint32_t)MAT_BYTES : 0u;
    const uint32_t bbase = (uint32_t)(BSLOT * MAT_BYTES);

    copy_chunk(0, 0); CP_COMMIT();

    for (int ch = 0; ch < NCHUNK; ch++) {
        const int s = ch & 1;
        if (ch < NCHUNK - 1) {
            copy_chunk(ch + 1, s ^ 1);
            CP_COMMIT();
            CP_WAIT(1);
        } else {
            CP_WAIT(0);
        }
        __syncthreads();

        const uint32_t sb = smem_base + s * STAGE_BYTES(PASS);
#pragma unroll
        for (int j = 0; j < 2; j++) {
            uint32_t a0[2][4];
#pragma unroll
            for (int t = 0; t < 2; t++) {
                uint32_t off = (uint32_t)((arow + t * 16) * 64 + (acol + j * 2) * 16);
                uint32_t sw  = off ^ ((off >> 3) & 0x30);
                ldsm4(a0[t], sb + abase + sw);
            }
#pragma unroll
            for (int q = 0; q < 4; q++) {
                uint32_t b[4];
                uint32_t off = (uint32_t)((brow + q * 16) * 64 + (bcol + j * 2) * 16);
                uint32_t sw  = off ^ ((off >> 3) & 0x30);
                ldsm4(b, sb + bbase + sw);
#pragma unroll
                for (int t = 0; t < 2; t++)
#pragma unroll
                    for (int h = 0; h < 2; h++)
                        mma16816(acc[t][q * 2 + h], a0[t], b[h * 2], b[h * 2 + 1]);
            }
        }
        __syncthreads();   // stage s must drain before it is refilled
    }

    // ---- epilogue: fragments -> fp32 smem (stride 132) -> fold / writeout ----
    const int er = lane >> 2;
    const int ec = (lane & 3) * 2;
    float* ef = (float*)smem;
#pragma unroll
    for (int t = 0; t < 2; t++)
#pragma unroll
        for (int nt = 0; nt < 8; nt++) {
            int row = wm * 32 + t * 16 + er;
#pragma unroll
            for (int hlf = 0; hlf < 2; hlf++) {
                float f0 = acc[t][nt][hlf * 2 + 0];
                float f1 = acc[t][nt][hlf * 2 + 1];
                int rr = (row + hlf * 8) * 132;
                if (PASS == 1) {
                    // local col: wn=0 -> w' block (0..63), wn=1 -> mirror block
                    int col = wn * 64 + nt * 8 + ec;
                    *(float2*)&ef[rr + col] = make_float2(f0, f1);
                } else {
                    int col = 2 * (nt * 8 + ec) + wn;   // interleave parities
                    ef[rr + col]     = f0 * 0.00390625f;   // 1/256 scale fixup
                    ef[rr + col + 2] = f1 * 0.00390625f;
                }
            }
        }
    __syncthreads();

    const int r = tid >> 1, half = tid & 1;
    if (PASS == 1) {
        // fold: col c (w' = n0+c) pairs with col 127-c (w = 511-n0-c)
        const int kp = parity * 256 + m0 + r;
        size_t base = ((size_t)p * NN + kp) * NH + n0 + half * 32;
        const float* row = ef + r * 132;
#pragma unroll
        for (int g4 = 0; g4 < 4; g4++) {
            union { __half h[8]; uint4 u; } pe, po;
#pragma unroll
            for (int jj = 0; jj < 8; jj++) {
                int c = half * 32 + g4 * 8 + jj;
                float u = row[c];
                float v = row[127 - c];
                pe.h[jj] = __float2half(u + v);
                po.h[jj] = __float2half(u - v);
            }
            *(uint4*)&g_te[base + g4 * 8] = pe.u;
            *(uint4*)&g_to[base + g4 * 8] = po.u;
        }
    } else {
        const int kp = m0 + r;                       // permuted k index
        const int k  = (kp < 256) ? 2 * kp : 2 * kp - 511;
        const int b = p / 3, c = p % 3;
        const int l0 = 2 * n0;
        float* dst = Out + (((size_t)b * NN + k) * NN + l0 + half * 64) * 3 + c;
#pragma unroll 8
        for (int j = 0; j < 64; j++)
            dst[j * 3] = ef[r * 132 + half * 64 + j];
    }
}

// ---------------- launcher ----------------
extern "C" void kernel_launch(void* const* d_in, const int* in_sizes, int n_in,
                              void* d_out, int out_size) {
    (void)in_sizes; (void)n_in; (void)out_size;
    const float* x = (const float*)d_in[0];
    float* out = (float*)d_out;

    cudaFuncSetAttribute(gemm_hmma_kernel<1>,
                         cudaFuncAttributeMaxDynamicSharedMemorySize, GEMM_SMEM_TOTAL);
    cudaFuncSetAttribute(gemm_hmma_kernel<2>,
                         cudaFuncAttributeMaxDynamicSharedMemorySize, GEMM_SMEM_TOTAL);

    init_dct_half<<<256, 256>>>();
    fold_split_x<<<dim3(16, 8, NB), 256>>>(x);

    gemm_hmma_kernel<1><<<dim3(4, 4, NPLANES), 256, GEMM_SMEM_TOTAL>>>(nullptr);
    gemm_hmma_kernel<2><<<dim3(4, 4, NPLANES), 256, GEMM_SMEM_TOTAL>>>(out);
}

// round 15
// speedup vs baseline: 1.9969x; 1.9969x over previous
#include <cuda_runtime.h>
#include <cuda_fp16.h>
#include <cstdint>
#include <math.h>

#define NB 32
#define NN 512
#define NH 256
#define NPLANES 96
#define HALF ((size_t)NN * NH)   // 512*256

// ---------------- device globals (no allocation allowed) ----------------
// DCT matrices (x16 vs orthonormal: element = cos), single-rounded fp16
__device__ __align__(1024) __half g_De[NH * NH];   // even-k rows [r][h]
__device__ __align__(1024) __half g_Do[NH * NH];   // odd-k rows
// folded input, single-rounded fp16: [p=3b+c][w][h']
__device__ __align__(1024) __half g_xe[NPLANES * HALF], g_xo[NPLANES * HALF];
// folded intermediate (x16 scale), fp16: [p][k'][w']  (k' = parity*256 + half-index)
__device__ __align__(1024) __half g_te[NPLANES * HALF], g_to[NPLANES * HALF];
// pass-2 planar result (final scale), fp32, permuted rows: [p][k'][l]
__device__ __align__(1024) float  g_y[NPLANES * (size_t)NN * NN];

// ---------------- helpers ----------------
__device__ __forceinline__ uint32_t smem_to_u32(const void* smem_ptr) {
    uint32_t addr;
    asm("{ .reg .u64 tmp; cvta.to.shared.u64 tmp, %1; cvt.u32.u64 %0, tmp; }"
        : "=r"(addr) : "l"(smem_ptr));
    return addr;
}
#define CP_ASYNC_16(saddr, gptr) \
    asm volatile("cp.async.cg.shared.global [%0], [%1], 16;" \
        :: "r"((uint32_t)(saddr)), "l"(gptr) : "memory")
#define CP_COMMIT() asm volatile("cp.async.commit_group;" ::: "memory")
#define CP_WAIT(n)  asm volatile("cp.async.wait_group %0;" :: "n"(n) : "memory")

__device__ __forceinline__ void ldsm4(uint32_t r[4], uint32_t addr) {
    asm volatile("ldmatrix.sync.aligned.m8n8.x4.shared.b16 {%0,%1,%2,%3}, [%4];"
        : "=r"(r[0]), "=r"(r[1]), "=r"(r[2]), "=r"(r[3]) : "r"(addr));
}
__device__ __forceinline__ void mma16816(float c[4], const uint32_t a[4],
                                         uint32_t b0, uint32_t b1) {
    asm volatile(
        "mma.sync.aligned.m16n8k16.row.col.f32.f16.f16.f32 "
        "{%0,%1,%2,%3}, {%4,%5,%6,%7}, {%8,%9}, {%0,%1,%2,%3};"
        : "+f"(c[0]), "+f"(c[1]), "+f"(c[2]), "+f"(c[3])
        : "r"(a[0]), "r"(a[1]), "r"(a[2]), "r"(a[3]), "r"(b0), "r"(b1));
}

// -------- kernel 0: half-size DCT matrices (x16 scale), fp16 --------
__global__ void init_dct_half() {
    int idx = blockIdx.x * blockDim.x + threadIdx.x;   // 256*256 threads
    int r = idx >> 8;
    int h = idx & 255;
    int me = ((2 * h + 1) * (2 * r)) & 2047;
    float ve = cospif((float)me * (1.0f / 1024.0f));
    if (r == 0) ve *= 0.70710678118654752440f;
    g_De[idx] = __float2half(ve);
    int mo = ((2 * h + 1) * (2 * r + 1)) & 2047;
    g_Do[idx] = __float2half(cospif((float)mo * (1.0f / 1024.0f)));
}

// -------- kernel 1: de-interleave + transpose + h-fold + single fp16 round --------
// x[b][h][w][c] fp32 -> xe/xo fp16 [p=3b+c][w][h'<256]
__global__ __launch_bounds__(256) void fold_split_x(const float* __restrict__ x) {
    __shared__ float tA[3][32][33];
    __shared__ float tB[3][32][33];
    const int tid = threadIdx.x;
    const int b = blockIdx.z, h0 = blockIdx.y * 32, w0 = blockIdx.x * 32;
    const float* baseA = x + (((size_t)b * NN + h0) * NN + w0) * 3;
    const float* baseB = x + (((size_t)b * NN + (480 - h0)) * NN + w0) * 3;

    for (int i = tid; i < 768; i += 256) {             // 32 rows x 24 float4
        int row = i / 24, f4 = i % 24;
        float4 va = *(const float4*)(baseA + (size_t)row * NN * 3 + f4 * 4);
        float4 vb = *(const float4*)(baseB + (size_t)row * NN * 3 + f4 * 4);
        int f = f4 * 4;
        tA[(f + 0) % 3][(f + 0) / 3][row] = va.x;
        tA[(f + 1) % 3][(f + 1) / 3][row] = va.y;
        tA[(f + 2) % 3][(f + 2) / 3][row] = va.z;
        tA[(f + 3) % 3][(f + 3) / 3][row] = va.w;
        tB[(f + 0) % 3][(f + 0) / 3][row] = vb.x;
        tB[(f + 1) % 3][(f + 1) / 3][row] = vb.y;
        tB[(f + 2) % 3][(f + 2) / 3][row] = vb.z;
        tB[(f + 3) % 3][(f + 3) / 3][row] = vb.w;
    }
    __syncthreads();

    const int wl = tid >> 3;
    const int hs = (tid & 7) * 4;
#pragma unroll
    for (int c = 0; c < 3; c++) {
        size_t p = (size_t)(b * 3 + c);
        size_t dst = (p * NN + (w0 + wl)) * NH + h0 + hs;
        union { __half v[4]; uint2 u; } ue, uo;
#pragma unroll
        for (int j = 0; j < 4; j++) {
            int hr = hs + j;
            float a = tA[c][wl][hr];
            float m = tB[c][wl][31 - hr];     // x[511-(h0+hr)]
            ue.v[j] = __float2half(a + m);
            uo.v[j] = __float2half(a - m);
        }
        *(uint2*)&g_xe[dst] = ue.u;
        *(uint2*)&g_xo[dst] = uo.u;
    }
}

// ---------------- HMMA GEMM, K=256, single fp16 product ----------------
// PASS 1: t[k'][w] = (De|Do) @ (xe|xo); CTA covers w'-tile AND its mirror,
//         epilogue folds w <-> 511-w and writes te/to fp16 directly.
// PASS 2: g_y[k'][l] = (te|to) @ (De|Do)^T, parity-interleaved columns, x(1/256),
//         coalesced planar fp32 writes (channel interleave deferred to kernel below).
// stage slots (8KB each, 128 rows x 64B, SW64):
//   PASS1: 0=M  1=X(two 64-row blocks)   PASS2: 0=te 1=to 2=B(De|Do)
#define MAT_BYTES   8192
#define STAGE_BYTES(P) ((P) == 1 ? 16384 : 24576)
#define NCHUNK      8
#define GEMM_SMEM_TOTAL 69632   // epilogue 128*132*4 = 67584 dominates

template <int PASS>
__global__ __launch_bounds__(256, 2)
void gemm_hmma_kernel() {
    extern __shared__ char smem[];
    const uint32_t smem_base = smem_to_u32(smem);
    const int tid  = threadIdx.x;
    const int wid  = tid >> 5;
    const int lane = tid & 31;
    const int p  = blockIdx.z;

    const __half *pA0, *pA1 = nullptr, *pB0, *pB0b;
    int m0, n0, parity = 0;
    if (PASS == 1) {
        parity = blockIdx.y >> 1;
        m0 = (blockIdx.y & 1) * 128;
        n0 = blockIdx.x * 64;                  // w' tile base (64 wide + mirror)
        pA0 = (parity ? g_Do : g_De) + (size_t)m0 * NH;
        const __half* xpar = (parity ? g_xo : g_xe) + (size_t)p * HALF;
        pB0  = xpar + (size_t)n0 * NH;                    // rows 0..63: w' = n0+r
        pB0b = xpar + ((size_t)(384 - n0)) * NH;          // rows 64..127: w = 448-n0+(r-64)
    } else {
        m0 = blockIdx.y * 128;                 // k' tile
        n0 = blockIdx.x * 64;                  // l'' offset (final l tile = 2*n0)
        pA0 = g_te + (size_t)p * HALF + (size_t)m0 * NH;
        pA1 = g_to + (size_t)p * HALF + (size_t)m0 * NH;
        pB0  = g_De + (size_t)n0 * NH;                    // rows 0..63
        pB0b = g_Do + ((long long)n0 - 64) * NH;          // rows 64..127
    }

    const int wm = wid & 3;
    const int wn = wid >> 2;

    float acc[2][8][4];
#pragma unroll
    for (int t = 0; t < 2; t++)
#pragma unroll
        for (int nt = 0; nt < 8; nt++)
#pragma unroll
            for (int r = 0; r < 4; r++) acc[t][nt][r] = 0.0f;

    constexpr int NSLOT = (PASS == 1) ? 2 : 3;
    constexpr int NCOPY = NSLOT * 512;
    constexpr int BSLOT = NSLOT - 1;
    auto copy_chunk = [&](int ch, int s) {
        const int k0c = ch * 32;
        const uint32_t sb = smem_base + s * STAGE_BYTES(PASS);
        for (int i = tid; i < NCOPY; i += 256) {
            int slot = i >> 9;
            int seg  = i & 511;
            int r    = seg >> 2;
            int c16  = seg & 3;
            const __half* src;
            if (slot == 0)          src = pA0;
            else if (slot < BSLOT)  src = pA1;
            else                    src = (r < 64) ? pB0 : pB0b;
            uint32_t off = (uint32_t)(r * 64 + c16 * 16);
            uint32_t sw  = off ^ ((off >> 3) & 0x30);   // SW64
            CP_ASYNC_16(sb + slot * MAT_BYTES + sw, src + (size_t)r * NH + k0c + c16 * 8);
        }
    };

    // ldmatrix lane geometry (SW64, 64B rows)
    const int arow = wm * 32 + (lane & 15);
    const int acol = lane >> 4;
    const int brow = wn * 64 + (lane & 7) + ((lane >> 4) << 3);
    const int bcol = (lane >> 3) & 1;
    const uint32_t abase = (PASS == 2 && wn) ? (uint32_t)MAT_BYTES : 0u;
    const uint32_t bbase = (uint32_t)(BSLOT * MAT_BYTES);

    copy_chunk(0, 0); CP_COMMIT();

    for (int ch = 0; ch < NCHUNK; ch++) {
        const int s = ch & 1;
        if (ch < NCHUNK - 1) {
            copy_chunk(ch + 1, s ^ 1);
            CP_COMMIT();
            CP_WAIT(1);
        } else {
            CP_WAIT(0);
        }
        __syncthreads();

        const uint32_t sb = smem_base + s * STAGE_BYTES(PASS);
#pragma unroll
        for (int j = 0; j < 2; j++) {
            uint32_t a0[2][4];
#pragma unroll
            for (int t = 0; t < 2; t++) {
                uint32_t off = (uint32_t)((arow + t * 16) * 64 + (acol + j * 2) * 16);
                uint32_t sw  = off ^ ((off >> 3) & 0x30);
                ldsm4(a0[t], sb + abase + sw);
            }
#pragma unroll
            for (int q = 0; q < 4; q++) {
                uint32_t b[4];
                uint32_t off = (uint32_t)((brow + q * 16) * 64 + (bcol + j * 2) * 16);
                uint32_t sw  = off ^ ((off >> 3) & 0x30);
                ldsm4(b, sb + bbase + sw);
#pragma unroll
                for (int t = 0; t < 2; t++)
#pragma unroll
                    for (int h = 0; h < 2; h++)
                        mma16816(acc[t][q * 2 + h], a0[t], b[h * 2], b[h * 2 + 1]);
            }
        }
        __syncthreads();   // stage s must drain before it is refilled
    }

    // ---- epilogue: fragments -> fp32 smem (stride 132) -> fold / writeout ----
    const int er = lane >> 2;
    const int ec = (lane & 3) * 2;
    float* ef = (float*)smem;
#pragma unroll
    for (int t = 0; t < 2; t++)
#pragma unroll
        for (int nt = 0; nt < 8; nt++) {
            int row = wm * 32 + t * 16 + er;
#pragma unroll
            for (int hlf = 0; hlf < 2; hlf++) {
                float f0 = acc[t][nt][hlf * 2 + 0];
                float f1 = acc[t][nt][hlf * 2 + 1];
                int rr = (row + hlf * 8) * 132;
                if (PASS == 1) {
                    // local col: wn=0 -> w' block (0..63), wn=1 -> mirror block
                    int col = wn * 64 + nt * 8 + ec;
                    *(float2*)&ef[rr + col] = make_float2(f0, f1);
                } else {
                    int col = 2 * (nt * 8 + ec) + wn;   // interleave parities
                    ef[rr + col]     = f0 * 0.00390625f;   // 1/256 scale fixup
                    ef[rr + col + 2] = f1 * 0.00390625f;
                }
            }
        }
    __syncthreads();

    const int r = tid >> 1, half = tid & 1;
    if (PASS == 1) {
        // fold: col c (w' = n0+c) pairs with col 127-c (w = 511-n0-c)
        const int kp = parity * 256 + m0 + r;
        size_t base = ((size_t)p * NN + kp) * NH + n0 + half * 32;
        const float* row = ef + r * 132;
#pragma unroll
        for (int g4 = 0; g4 < 4; g4++) {
            union { __half h[8]; uint4 u; } pe, po;
#pragma unroll
            for (int jj = 0; jj < 8; jj++) {
                int c = half * 32 + g4 * 8 + jj;
                float u = row[c];
                float v = row[127 - c];
                pe.h[jj] = __float2half(u + v);
                po.h[jj] = __float2half(u - v);
            }
            *(uint4*)&g_te[base + g4 * 8] = pe.u;
            *(uint4*)&g_to[base + g4 * 8] = po.u;
        }
    } else {
        // coalesced planar write: g_y[p][kp = m0+r][2*n0 + 0..127]
        float* dst = g_y + (((size_t)p * NN) + (m0 + r)) * NN + 2 * n0 + half * 64;
#pragma unroll
        for (int j = 0; j < 16; j++)
            *(float4*)(dst + j * 4) = *(const float4*)(ef + r * 132 + half * 64 + j * 4);
    }
}

// -------- kernel 4: channel interleave + k un-permute, fully coalesced --------
// g_y[3b+c][kp][l] fp32 -> out[b][k][l][c]
__global__ __launch_bounds__(256) void interleave_out(float* __restrict__ Out) {
    __shared__ float buf[3][512];
    const int tid = threadIdx.x;
    const int k = blockIdx.x;      // 0..511
    const int b = blockIdx.y;      // 0..31
    const int kp = (k & 1) ? ((k + 511) >> 1) : (k >> 1);

    for (int i = tid; i < 384; i += 256) {           // 3 rows x 128 float4
        int c = i >> 7, f4 = i & 127;
        *(float4*)&buf[c][f4 * 4] =
            *(const float4*)&g_y[(((size_t)(3 * b + c)) * NN + kp) * NN + f4 * 4];
    }
    __syncthreads();

    float* dst = Out + ((size_t)b * NN + k) * NN * 3;
    for (int i = tid; i < 384; i += 256) {           // 1536 floats = 384 float4
        int e0 = i * 4;
        float4 v;
        v.x = buf[(e0 + 0) % 3][(e0 + 0) / 3];
        v.y = buf[(e0 + 1) % 3][(e0 + 1) / 3];
        v.z = buf[(e0 + 2) % 3][(e0 + 2) / 3];
        v.w = buf[(e0 + 3) % 3][(e0 + 3) / 3];
        *(float4*)&dst[e0] = v;
    }
}

// ---------------- launcher ----------------
extern "C" void kernel_launch(void* const* d_in, const int* in_sizes, int n_in,
                              void* d_out, int out_size) {
    (void)in_sizes; (void)n_in; (void)out_size;
    const float* x = (const float*)d_in[0];
    float* out = (float*)d_out;

    cudaFuncSetAttribute(gemm_hmma_kernel<1>,
                         cudaFuncAttributeMaxDynamicSharedMemorySize, GEMM_SMEM_TOTAL);
    cudaFuncSetAttribute(gemm_hmma_kernel<2>,
                         cudaFuncAttributeMaxDynamicSharedMemorySize, GEMM_SMEM_TOTAL);

    init_dct_half<<<256, 256>>>();
    fold_split_x<<<dim3(16, 8, NB), 256>>>(x);

    gemm_hmma_kernel<1><<<dim3(4, 4, NPLANES), 256, GEMM_SMEM_TOTAL>>>();
    gemm_hmma_kernel<2><<<dim3(4, 4, NPLANES), 256, GEMM_SMEM_TOTAL>>>();
    interleave_out<<<dim3(NN, NB), 256>>>(out);
}

// round 17
// speedup vs baseline: 2.5140x; 1.2590x over previous
#include <cuda_runtime.h>
#include <cuda_fp16.h>
#include <cstdint>
#include <math.h>

#define NB 32
#define NN 512
#define NH 256
#define NPLANES 96
#define HALF ((size_t)NN * NH)   // 512*256

// ---------------- device globals (no allocation allowed) ----------------
// DCT matrices (x16 vs orthonormal: element = cos), single-rounded fp16
__device__ __align__(1024) __half g_De[NH * NH];   // even-k rows [r][h]
__device__ __align__(1024) __half g_Do[NH * NH];   // odd-k rows
// folded input, single-rounded fp16: [p=3b+c][w][h']
__device__ __align__(1024) __half g_xe[NPLANES * HALF], g_xo[NPLANES * HALF];
// folded intermediate (x16 scale), fp16: [p][k'][w']  (k' = parity*256 + half-index)
__device__ __align__(1024) __half g_te[NPLANES * HALF], g_to[NPLANES * HALF];
// pass-2 planar result (final scale), fp16, permuted rows: [p][k'][l]
__device__ __align__(1024) __half g_y16[NPLANES * (size_t)NN * NN];

// ---------------- helpers ----------------
__device__ __forceinline__ uint32_t smem_to_u32(const void* smem_ptr) {
    uint32_t addr;
    asm("{ .reg .u64 tmp; cvta.to.shared.u64 tmp, %1; cvt.u32.u64 %0, tmp; }"
        : "=r"(addr) : "l"(smem_ptr));
    return addr;
}
#define CP_ASYNC_16(saddr, gptr) \
    asm volatile("cp.async.cg.shared.global [%0], [%1], 16;" \
        :: "r"((uint32_t)(saddr)), "l"(gptr) : "memory")
#define CP_COMMIT() asm volatile("cp.async.commit_group;" ::: "memory")
#define CP_WAIT(n)  asm volatile("cp.async.wait_group %0;" :: "n"(n) : "memory")

__device__ __forceinline__ void ldsm4(uint32_t r[4], uint32_t addr) {
    asm volatile("ldmatrix.sync.aligned.m8n8.x4.shared.b16 {%0,%1,%2,%3}, [%4];"
        : "=r"(r[0]), "=r"(r[1]), "=r"(r[2]), "=r"(r[3]) : "r"(addr));
}
__device__ __forceinline__ void mma16816(float c[4], const uint32_t a[4],
                                         uint32_t b0, uint32_t b1) {
    asm volatile(
        "mma.sync.aligned.m16n8k16.row.col.f32.f16.f16.f32 "
        "{%0,%1,%2,%3}, {%4,%5,%6,%7}, {%8,%9}, {%0,%1,%2,%3};"
        : "+f"(c[0]), "+f"(c[1]), "+f"(c[2]), "+f"(c[3])
        : "r"(a[0]), "r"(a[1]), "r"(a[2]), "r"(a[3]), "r"(b0), "r"(b1));
}
#define SW128(off) ((off) ^ (((off) >> 3) & 0x70))

// -------- kernel 0: half-size DCT matrices (x16 scale), fp16 --------
__global__ void init_dct_half() {
    int idx = blockIdx.x * blockDim.x + threadIdx.x;   // 256*256 threads
    int r = idx >> 8;
    int h = idx & 255;
    int me = ((2 * h + 1) * (2 * r)) & 2047;
    float ve = cospif((float)me * (1.0f / 1024.0f));
    if (r == 0) ve *= 0.70710678118654752440f;
    g_De[idx] = __float2half(ve);
    int mo = ((2 * h + 1) * (2 * r + 1)) & 2047;
    g_Do[idx] = __float2half(cospif((float)mo * (1.0f / 1024.0f)));
}

// -------- kernel 1: de-interleave + transpose + h-fold + single fp16 round --------
// x[b][h][w][c] fp32 -> xe/xo fp16 [p=3b+c][w][h'<256]
__global__ __launch_bounds__(256) void fold_split_x(const float* __restrict__ x) {
    __shared__ float tA[3][32][33];
    __shared__ float tB[3][32][33];
    const int tid = threadIdx.x;
    const int b = blockIdx.z, h0 = blockIdx.y * 32, w0 = blockIdx.x * 32;
    const float* baseA = x + (((size_t)b * NN + h0) * NN + w0) * 3;
    const float* baseB = x + (((size_t)b * NN + (480 - h0)) * NN + w0) * 3;

    for (int i = tid; i < 768; i += 256) {             // 32 rows x 24 float4
        int row = i / 24, f4 = i % 24;
        float4 va = *(const float4*)(baseA + (size_t)row * NN * 3 + f4 * 4);
        float4 vb = *(const float4*)(baseB + (size_t)row * NN * 3 + f4 * 4);
        int f = f4 * 4;
        tA[(f + 0) % 3][(f + 0) / 3][row] = va.x;
        tA[(f + 1) % 3][(f + 1) / 3][row] = va.y;
        tA[(f + 2) % 3][(f + 2) / 3][row] = va.z;
        tA[(f + 3) % 3][(f + 3) / 3][row] = va.w;
        tB[(f + 0) % 3][(f + 0) / 3][row] = vb.x;
        tB[(f + 1) % 3][(f + 1) / 3][row] = vb.y;
        tB[(f + 2) % 3][(f + 2) / 3][row] = vb.z;
        tB[(f + 3) % 3][(f + 3) / 3][row] = vb.w;
    }
    __syncthreads();

    const int wl = tid >> 3;
    const int hs = (tid & 7) * 4;
#pragma unroll
    for (int c = 0; c < 3; c++) {
        size_t p = (size_t)(b * 3 + c);
        size_t dst = (p * NN + (w0 + wl)) * NH + h0 + hs;
        union { __half v[4]; uint2 u; } ue, uo;
#pragma unroll
        for (int j = 0; j < 4; j++) {
            int hr = hs + j;
            float a = tA[c][wl][hr];
            float m = tB[c][wl][31 - hr];     // x[511-(h0+hr)]
            ue.v[j] = __float2half(a + m);
            uo.v[j] = __float2half(a - m);
        }
        *(uint2*)&g_xe[dst] = ue.u;
        *(uint2*)&g_xo[dst] = uo.u;
    }
}

// ---------------- HMMA GEMM, K=256 (4 chunks of 64), single fp16 product ----------------
// PASS 1: t[k'][w] = (De|Do) @ (xe|xo); CTA covers w'-tile AND its mirror,
//         epilogue folds w <-> 511-w and writes te/to fp16 directly.
// PASS 2: g_y16[k'][l] = (te|to) @ (De|Do)^T, parity-interleaved cols, x(1/256).
// stage slots (16KB each: 128 rows x 128B, SW128):
//   PASS1: 0=M  1=X(two 64-row blocks)   PASS2: 0=te 1=to 2=B(De|Do)
#define MAT_BYTES   16384
#define NCHUNK      4
#define P1_STAGE    32768
#define P2_STAGE    49152
#define P1_SMEM     69632    // epilogue fp32 128*132*4 = 67584 dominates
#define P2_SMEM     98304    // 2 stages of 48KB

template <int PASS>
__global__ __launch_bounds__(256, 2)
void gemm_hmma_kernel() {
    extern __shared__ char smem[];
    const uint32_t smem_base = smem_to_u32(smem);
    const int tid  = threadIdx.x;
    const int wid  = tid >> 5;
    const int lane = tid & 31;
    const int p  = blockIdx.z;

    const __half *pA0, *pA1 = nullptr, *pB0, *pB0b;
    int m0, n0, parity = 0;
    if (PASS == 1) {
        parity = blockIdx.y >> 1;
        m0 = (blockIdx.y & 1) * 128;
        n0 = blockIdx.x * 64;                  // w' tile base (64 wide + mirror)
        pA0 = (parity ? g_Do : g_De) + (size_t)m0 * NH;
        const __half* xpar = (parity ? g_xo : g_xe) + (size_t)p * HALF;
        pB0  = xpar + (size_t)n0 * NH;                    // rows 0..63: w' = n0+r
        pB0b = xpar + ((size_t)(384 - n0)) * NH;          // rows 64..127: mirror block
    } else {
        m0 = blockIdx.y * 128;                 // k' tile
        n0 = blockIdx.x * 64;                  // l'' offset (final l tile = 2*n0)
        pA0 = g_te + (size_t)p * HALF + (size_t)m0 * NH;
        pA1 = g_to + (size_t)p * HALF + (size_t)m0 * NH;
        pB0  = g_De + (size_t)n0 * NH;                    // rows 0..63
        pB0b = g_Do + ((long long)n0 - 64) * NH;          // rows 64..127
    }

    const int wm = wid & 3;
    const int wn = wid >> 2;

    float acc[2][8][4];
#pragma unroll
    for (int t = 0; t < 2; t++)
#pragma unroll
        for (int nt = 0; nt < 8; nt++)
#pragma unroll
            for (int r = 0; r < 4; r++) acc[t][nt][r] = 0.0f;

    constexpr int NSLOT = (PASS == 1) ? 2 : 3;
    constexpr int NCOPY = NSLOT * 1024;          // 128 rows x 8 16B-segs per slot
    constexpr int BSLOT = NSLOT - 1;
    constexpr uint32_t STAGE = (PASS == 1) ? P1_STAGE : P2_STAGE;
    auto copy_chunk = [&](int ch, int s) {
        const int k0c = ch * 64;
        const uint32_t sb = smem_base + s * STAGE;
        for (int i = tid; i < NCOPY; i += 256) {
            int slot = i >> 10;
            int seg  = i & 1023;
            int r    = seg >> 3;
            int c16  = seg & 7;
            const __half* src;
            if (slot == 0)          src = pA0;
            else if (slot < BSLOT)  src = pA1;
            else                    src = (r < 64) ? pB0 : pB0b;
            uint32_t off = (uint32_t)(r * 128 + c16 * 16);
            CP_ASYNC_16(sb + slot * MAT_BYTES + SW128(off),
                        src + (size_t)r * NH + k0c + c16 * 8);
        }
    };

    // ldmatrix lane geometry (SW128, 128B rows)
    const int arow = wm * 32 + (lane & 15);
    const int acol = lane >> 4;
    const int brow = wn * 64 + (lane & 7) + ((lane >> 4) << 3);
    const int bcol = (lane >> 3) & 1;
    const uint32_t abase = (PASS == 2 && wn) ? (uint32_t)MAT_BYTES : 0u;
    const uint32_t bbase = (uint32_t)(BSLOT * MAT_BYTES);

    copy_chunk(0, 0); CP_COMMIT();

    for (int ch = 0; ch < NCHUNK; ch++) {
        const int s = ch & 1;
        if (ch < NCHUNK - 1) {
            copy_chunk(ch + 1, s ^ 1);
            CP_COMMIT();
            CP_WAIT(1);
        } else {
            CP_WAIT(0);
        }
        __syncthreads();

        const uint32_t sb = smem_base + s * STAGE;
#pragma unroll
        for (int j = 0; j < 4; j++) {
            uint32_t a0[2][4];
#pragma unroll
            for (int t = 0; t < 2; t++) {
                uint32_t off = (uint32_t)((arow + t * 16) * 128 + (acol + j * 2) * 16);
                ldsm4(a0[t], sb + abase + SW128(off));
            }
#pragma unroll
            for (int q = 0; q < 4; q++) {
                uint32_t b[4];
                uint32_t off = (uint32_t)((brow + q * 16) * 128 + (bcol + j * 2) * 16);
                ldsm4(b, sb + bbase + SW128(off));
#pragma unroll
                for (int t = 0; t < 2; t++)
#pragma unroll
                    for (int h = 0; h < 2; h++)
                        mma16816(acc[t][q * 2 + h], a0[t], b[h * 2], b[h * 2 + 1]);
            }
        }
        __syncthreads();   // stage s must drain before it is refilled
    }

    // ---- epilogue ----
    const int er = lane >> 2;
    const int ec = (lane & 3) * 2;
    const int r = tid >> 1, half = tid & 1;

    if (PASS == 1) {
        float* ef = (float*)smem;               // stride 132 floats
#pragma unroll
        for (int t = 0; t < 2; t++)
#pragma unroll
            for (int nt = 0; nt < 8; nt++) {
                int row = wm * 32 + t * 16 + er;
                int col = wn * 64 + nt * 8 + ec;
#pragma unroll
                for (int hlf = 0; hlf < 2; hlf++)
                    *(float2*)&ef[(row + hlf * 8) * 132 + col] =
                        make_float2(acc[t][nt][hlf * 2], acc[t][nt][hlf * 2 + 1]);
            }
        __syncthreads();
        // fold: col c (w' = n0+c) pairs with col 127-c (w = 511-n0-c)
        const int kp = parity * 256 + m0 + r;
        size_t base = ((size_t)p * NN + kp) * NH + n0 + half * 32;
        const float* row = ef + r * 132;
#pragma unroll
        for (int g4 = 0; g4 < 4; g4++) {
            union { __half h[8]; uint4 u; } pe, po;
#pragma unroll
            for (int jj = 0; jj < 8; jj++) {
                int c = half * 32 + g4 * 8 + jj;
                float u = row[c];
                float v = row[127 - c];
                pe.h[jj] = __float2half(u + v);
                po.h[jj] = __float2half(u - v);
            }
            *(uint4*)&g_te[base + g4 * 8] = pe.u;
            *(uint4*)&g_to[base + g4 * 8] = po.u;
        }
    } else {
        __half* eh = (__half*)smem;             // stride 136 halfs (272B rows)
#pragma unroll
        for (int t = 0; t < 2; t++)
#pragma unroll
            for (int nt = 0; nt < 8; nt++) {
                int row = wm * 32 + t * 16 + er;
                int col = 2 * (nt * 8 + ec) + wn;   // parity interleave
#pragma unroll
                for (int hlf = 0; hlf < 2; hlf++) {
                    int rr = (row + hlf * 8) * 136;
                    eh[rr + col]     = __float2half(acc[t][nt][hlf * 2]     * 0.00390625f);
                    eh[rr + col + 2] = __float2half(acc[t][nt][hlf * 2 + 1] * 0.00390625f);
                }
            }
        __syncthreads();
        // coalesced planar fp16 write: g_y16[p][m0+r][2*n0 + 0..127]
        __half* dst = g_y16 + (((size_t)p * NN) + (m0 + r)) * NN + 2 * n0 + half * 64;
        const __half* srcrow = eh + r * 136 + half * 64;
#pragma unroll
        for (int j = 0; j < 8; j++)
            *(uint4*)(dst + j * 8) = *(const uint4*)(srcrow + j * 8);
    }
}

// -------- kernel 4: channel interleave + k un-permute + fp32 convert --------
// g_y16[3b+c][kp][l] fp16 -> out[b][k][l][c] fp32
__global__ __launch_bounds__(256) void interleave_out(float* __restrict__ Out) {
    __shared__ __half buf[3][520];
    const int tid = threadIdx.x;
    const int k = blockIdx.x;      // 0..511
    const int b = blockIdx.y;      // 0..31
    const int kp = (k & 1) ? ((k + 511) >> 1) : (k >> 1);

    for (int i = tid; i < 192; i += 256) {           // 3 rows x 64 uint4 (8 halfs)
        int c = i / 64, g8 = i % 64;
        *(uint4*)&buf[c][g8 * 8] =
            *(const uint4*)&g_y16[(((size_t)(3 * b + c)) * NN + kp) * NN + g8 * 8];
    }
    __syncthreads();

    float* dst = Out + ((size_t)b * NN + k) * NN * 3;
    for (int i = tid; i < 384; i += 256) {           // 1536 floats = 384 float4
        int e0 = i * 4;
        float4 v;
        v.x = __half2float(buf[(e0 + 0) % 3][(e0 + 0) / 3]);
        v.y = __half2float(buf[(e0 + 1) % 3][(e0 + 1) / 3]);
        v.z = __half2float(buf[(e0 + 2) % 3][(e0 + 2) / 3]);
        v.w = __half2float(buf[(e0 + 3) % 3][(e0 + 3) / 3]);
        *(float4*)&dst[e0] = v;
    }
}

// ---------------- launcher ----------------
extern "C" void kernel_launch(void* const* d_in, const int* in_sizes, int n_in,
                              void* d_out, int out_size) {
    (void)in_sizes; (void)n_in; (void)out_size;
    const float* x = (const float*)d_in[0];
    float* out = (float*)d_out;

    cudaFuncSetAttribute(gemm_hmma_kernel<1>,
                         cudaFuncAttributeMaxDynamicSharedMemorySize, P1_SMEM);
    cudaFuncSetAttribute(gemm_hmma_kernel<2>,
                         cudaFuncAttributeMaxDynamicSharedMemorySize, P2_SMEM);

    init_dct_half<<<256, 256>>>();
    fold_split_x<<<dim3(16, 8, NB), 256>>>(x);

    gemm_hmma_kernel<1><<<dim3(4, 4, NPLANES), 256, P1_SMEM>>>();
    gemm_hmma_kernel<2><<<dim3(4, 4, NPLANES), 256, P2_SMEM>>>();
    interleave_out<<<dim3(NN, NB), 256>>>(out);
}